// round 16
// baseline (speedup 1.0000x reference)
#include <cuda_runtime.h>
#include <cuda_fp16.h>
#include <math.h>
#include <stdint.h>

#define S 4096
#define H 1152
#define NH 16
#define HD 72
#define FF 4304
#define QKVN (3 * H)          // 3456
#define LN_EPS 1e-6f

// ---------------- scratch (allocation-free: device globals) ----------------
__device__ __half g_xnh[S * H];
__device__ __half g_qkvh[(size_t)S * QKVN];
__device__ __half g_attnh[S * H];
__device__ float  g_hid[S * H];
__device__ __half g_yh[S * H];
__device__ __half g_ffh[(size_t)S * FF];
__device__ __half g_wqkvh[(size_t)QKVN * H];
__device__ __half g_owh[H * H];
__device__ __half g_fc1h[(size_t)H * FF];
__device__ __half g_fc2h[(size_t)H * FF];
__device__ float  g_bqkv[QKVN];
__device__ int g_segs[S];
__device__ int g_sege[S];

// ---------------- weight conversion: float -> half ----------------
__global__ __launch_bounds__(256) void cvt_f2h(const float4* __restrict__ x,
                                               __half2* __restrict__ y, int n4) {
    int i = blockIdx.x * blockDim.x + threadIdx.x;
    if (i < n4) {
        float4 v = x[i];
        y[2 * i]     = __floats2half2_rn(v.x, v.y);
        y[2 * i + 1] = __floats2half2_rn(v.z, v.w);
    }
}

// 4 same-size tensors in one launch (blockIdx.y selects)
__global__ __launch_bounds__(256) void cvt_f2h4(const float4* __restrict__ x0,
                                                const float4* __restrict__ x1,
                                                const float4* __restrict__ x2,
                                                const float4* __restrict__ x3,
                                                __half2* __restrict__ y0,
                                                __half2* __restrict__ y1,
                                                __half2* __restrict__ y2,
                                                __half2* __restrict__ y3,
                                                int n4) {
    int i = blockIdx.x * blockDim.x + threadIdx.x;
    if (i >= n4) return;
    const float4* x; __half2* y;
    switch (blockIdx.y) {
        case 0: x = x0; y = y0; break;
        case 1: x = x1; y = y1; break;
        case 2: x = x2; y = y2; break;
        default: x = x3; y = y3; break;
    }
    float4 v = x[i];
    y[2 * i]     = __floats2half2_rn(v.x, v.y);
    y[2 * i + 1] = __floats2half2_rn(v.z, v.w);
}

__global__ __launch_bounds__(256) void pack_bias(const float* __restrict__ qb,
                                                 const float* __restrict__ kb,
                                                 const float* __restrict__ vb,
                                                 float* __restrict__ dst) {
    int i = blockIdx.x * blockDim.x + threadIdx.x;
    if (i < H) {
        dst[i] = qb[i];
        dst[H + i] = kb[i];
        dst[2 * H + i] = vb[i];
    }
}

// ---------------- single-pass LayerNorm (float2 loads, half2 stores) -------
#define H2 (H / 2)            // 576

__global__ __launch_bounds__(256) void ln_kernel_h(const float* __restrict__ x,
                                                   const float* __restrict__ g,
                                                   const float* __restrict__ b,
                                                   __half* __restrict__ y) {
    int row = blockIdx.x;
    int tid = threadIdx.x, lane = tid & 31, wid = tid >> 5;
    const float2* xr = (const float2*)(x + (size_t)row * H);

    float2 c0 = xr[tid];
    float2 c1 = xr[tid + 256];
    bool has2 = tid < (H2 - 512);     // tid < 64
    float2 c2 = has2 ? xr[tid + 512] : make_float2(0.f, 0.f);

    float s  = c0.x + c0.y + c1.x + c1.y + c2.x + c2.y;
    float ss = c0.x * c0.x + c0.y * c0.y + c1.x * c1.x + c1.y * c1.y
             + c2.x * c2.x + c2.y * c2.y;

#pragma unroll
    for (int ofs = 16; ofs > 0; ofs >>= 1) {
        s  += __shfl_xor_sync(0xffffffffu, s, ofs);
        ss += __shfl_xor_sync(0xffffffffu, ss, ofs);
    }
    __shared__ float sw[8], ssw[8], stat[2];
    if (lane == 0) { sw[wid] = s; ssw[wid] = ss; }
    __syncthreads();
    if (tid == 0) {
        float t = 0.f, tt = 0.f;
#pragma unroll
        for (int i = 0; i < 8; ++i) { t += sw[i]; tt += ssw[i]; }
        float mu = t * (1.0f / H);
        float var = tt * (1.0f / H) - mu * mu;
        stat[0] = mu;
        stat[1] = rsqrtf(var + LN_EPS);
    }
    __syncthreads();
    float mu = stat[0], inv = stat[1];

    const float2* g2 = (const float2*)g;
    const float2* b2 = (const float2*)b;
    __half* yr = y + (size_t)row * H;

    {
        float2 gv = g2[tid], bv = b2[tid];
        *(__half2*)&yr[tid * 2] = __floats2half2_rn(
            (c0.x - mu) * inv * gv.x + bv.x,
            (c0.y - mu) * inv * gv.y + bv.y);
    }
    {
        int i = tid + 256;
        float2 gv = g2[i], bv = b2[i];
        *(__half2*)&yr[i * 2] = __floats2half2_rn(
            (c1.x - mu) * inv * gv.x + bv.x,
            (c1.y - mu) * inv * gv.y + bv.y);
    }
    if (has2) {
        int i = tid + 512;
        float2 gv = g2[i], bv = b2[i];
        *(__half2*)&yr[i * 2] = __floats2half2_rn(
            (c2.x - mu) * inv * gv.x + bv.x,
            (c2.y - mu) * inv * gv.y + bv.y);
    }
}

// ---------------- document segment ranges (ids are sorted) ----------------
__global__ void doc_ranges(const int* __restrict__ ids, int* __restrict__ segs,
                           int* __restrict__ sege) {
    int i = blockIdx.x * blockDim.x + threadIdx.x;
    if (i >= S) return;
    int d = ids[i];
    int lo = 0, hi = S;
    while (lo < hi) { int mid = (lo + hi) >> 1; if (ids[mid] < d) lo = mid + 1; else hi = mid; }
    segs[i] = lo;
    lo = 0; hi = S;
    while (lo < hi) { int mid = (lo + hi) >> 1; if (ids[mid] <= d) lo = mid + 1; else hi = mid; }
    sege[i] = lo;
}

// ---------------- common mma / ldmatrix ----------------
__device__ __forceinline__ void mma_f16(float* c, const uint32_t* a, const uint32_t* b) {
    asm volatile(
        "mma.sync.aligned.m16n8k16.row.col.f32.f16.f16.f32 "
        "{%0,%1,%2,%3}, {%4,%5,%6,%7}, {%8,%9}, {%0,%1,%2,%3};"
        : "+f"(c[0]), "+f"(c[1]), "+f"(c[2]), "+f"(c[3])
        : "r"(a[0]), "r"(a[1]), "r"(a[2]), "r"(a[3]), "r"(b[0]), "r"(b[1]));
}

__device__ __forceinline__ void ldm_x4(uint32_t* r, uint32_t addr) {
    asm volatile("ldmatrix.sync.aligned.m8n8.x4.shared.b16 {%0,%1,%2,%3}, [%4];"
                 : "=r"(r[0]), "=r"(r[1]), "=r"(r[2]), "=r"(r[3]) : "r"(addr));
}
__device__ __forceinline__ void ldm_x2(uint32_t* r, uint32_t addr) {
    asm volatile("ldmatrix.sync.aligned.m8n8.x2.shared.b16 {%0,%1}, [%2];"
                 : "=r"(r[0]), "=r"(r[1]) : "r"(addr));
}

// ---------------- FP16 tensor-core GEMM (3-stage cp.async pipeline) --------
#define BM 128
#define BN 128
#define BKH 32
#define PITCH 40
#define NSTAGE 3
#define STAGE_HALF ((BM + BN) * PITCH)                 // halves per stage
#define GEMM_SMEM (NSTAGE * STAGE_HALF * 2)            // 61440 bytes

__device__ __forceinline__ void cp16(void* dst, const void* src, bool valid,
                                     const void* safe) {
    uint32_t d = (uint32_t)__cvta_generic_to_shared(dst);
    const void* s = valid ? src : safe;   // always in-bounds address
    int sz = valid ? 16 : 0;
    asm volatile("cp.async.cg.shared.global [%0], [%1], 16, %2;\n"
                 :: "r"(d), "l"(s), "r"(sz));
}

__global__ __launch_bounds__(256, 2) void gemm_f16(const __half* __restrict__ A,
                                                   const __half* __restrict__ W,
                                                   const float* __restrict__ bias,
                                                   const float* __restrict__ res,
                                                   float* __restrict__ C,
                                                   __half* __restrict__ Ch,
                                                   int M, int N, int K, int epi) {
    extern __shared__ __half sm[];
    // stage layout: [As rows BM][Ws rows BN], each row PITCH halves
    int tid = threadIdx.x;
    int lane = tid & 31, warp = tid >> 5;
    int wn = warp & 3;
    int wm = warp >> 2;
    int m0 = blockIdx.y * BM;
    int n0 = blockIdx.x * BN;

    int lr = tid >> 1;
    int lc = (tid & 1) * 2;

    const __half* Ab = A + (size_t)m0 * K;

    float acc[4][4][4];
#pragma unroll
    for (int i = 0; i < 4; ++i)
#pragma unroll
        for (int j = 0; j < 4; ++j)
#pragma unroll
            for (int l = 0; l < 4; ++l) acc[i][j][l] = 0.f;

    int nk = (K + BKH - 1) / BKH;

    // stage fill helper (as lambda to keep the proven access pattern)
    auto fill = [&](int stage, int t) {
        __half* aS = sm + stage * STAGE_HALF;
        __half* wS = aS + BM * PITCH;
        int ko = t * BKH;
#pragma unroll
        for (int cc = 0; cc < 2; ++cc) {
            int c = lc + cc;
            cp16(&aS[lr * PITCH + c * 8], Ab + (size_t)lr * K + ko + c * 8,
                 (ko + c * 8 + 8 <= K), A);
            cp16(&wS[lr * PITCH + c * 8], W + (size_t)(n0 + lr) * K + ko + c * 8,
                 ((n0 + lr) < N) && (ko + c * 8 + 8 <= K), W);
        }
    };

    // prologue: fill stages 0 and 1 (tiles 0 and 1)
    fill(0, 0);
    asm volatile("cp.async.commit_group;\n" ::: "memory");
    if (nk > 1) {
        fill(1, 1);
    }
    asm volatile("cp.async.commit_group;\n" ::: "memory");

    uint32_t aRowOff = (uint32_t)((wm * 64 + (lane & 15)) * PITCH + ((lane >> 4) << 3)) * 2;
    uint32_t bRowOff = (uint32_t)((wn * 32 + (lane & 7)) * PITCH + (((lane >> 3) & 1) << 3)) * 2;

    int fr = lane >> 2;
    int fc = lane & 3;

    for (int t = 0; t < nk; ++t) {
        // wait until at most 1 group pending: current tile's loads are done,
        // the next tile's prefetch may still be in flight.
        asm volatile("cp.async.wait_group 1;\n" ::: "memory");
        __syncthreads();

        int st = t % NSTAGE;
        if (t + 2 < nk) {
            fill((t + 2) % NSTAGE, t + 2);
        }
        asm volatile("cp.async.commit_group;\n" ::: "memory");

        uint32_t base = (uint32_t)__cvta_generic_to_shared(sm + st * STAGE_HALF);
        uint32_t aSm = base + aRowOff;
        uint32_t bSm = base + (uint32_t)(BM * PITCH * 2) + bRowOff;

#pragma unroll
        for (int kk = 0; kk < 2; ++kk) {
            uint32_t kB = (uint32_t)(kk * 16 * 2);
            uint32_t a[4][4], b[4][2];
#pragma unroll
            for (int mt = 0; mt < 4; ++mt)
                ldm_x4(a[mt], aSm + kB + (uint32_t)(mt * 16 * PITCH * 2));
#pragma unroll
            for (int nt = 0; nt < 4; ++nt)
                ldm_x2(b[nt], bSm + kB + (uint32_t)(nt * 8 * PITCH * 2));
#pragma unroll
            for (int mt = 0; mt < 4; ++mt)
#pragma unroll
                for (int nt = 0; nt < 4; ++nt)
                    mma_f16(acc[mt][nt], a[mt], b[nt]);
        }
        __syncthreads();   // all warps done reading stage st before it is refilled
    }

    // epilogue: column-pair vectorized stores (half2 / float2)
#pragma unroll
    for (int mt = 0; mt < 4; ++mt) {
        int row = m0 + wm * 64 + mt * 16 + fr;
#pragma unroll
        for (int nt = 0; nt < 4; ++nt) {
            int col = n0 + wn * 32 + nt * 8 + fc * 2;
            if (col >= N) continue;           // N even, col even -> col+1 < N too
            float b0 = bias[col];
            float b1 = bias[col + 1];
#pragma unroll
            for (int hh = 0; hh < 2; ++hh) {
                int r = row + (hh ? 8 : 0);
                float v0 = acc[mt][nt][hh * 2 + 0] + b0;
                float v1 = acc[mt][nt][hh * 2 + 1] + b1;
                if (epi == 1) {
                    float u0 = 0.7978845608028654f * (v0 + 0.044715f * v0 * v0 * v0);
                    float e0 = __expf(2.f * u0);
                    v0 = 0.5f * v0 * (2.f - 2.f / (e0 + 1.f));
                    float u1 = 0.7978845608028654f * (v1 + 0.044715f * v1 * v1 * v1);
                    float e1 = __expf(2.f * u1);
                    v1 = 0.5f * v1 * (2.f - 2.f / (e1 + 1.f));
                } else if (epi == 2) {
                    float2 rv = *(const float2*)&res[(size_t)r * N + col];
                    v0 += rv.x;
                    v1 += rv.y;
                }
                if (Ch) {
                    __half2 hv = __floats2half2_rn(v0, v1);
                    *(__half2*)&Ch[(size_t)r * N + col] = hv;
                } else {
                    float2 fv;
                    fv.x = v0; fv.y = v1;
                    *(float2*)&C[(size_t)r * N + col] = fv;
                }
            }
        }
    }
}

// ---------------- tensor-core flash attention (doc-masked) -----------------
#define AQT 64
#define AKT 64
#define QKP 88
#define VTP 72

__global__ __launch_bounds__(128) void attn_mma(const __half* __restrict__ QKV,
                                                const int* __restrict__ segs,
                                                const int* __restrict__ sege,
                                                __half* __restrict__ O) {
    __shared__ __half Qs[AQT][QKP];
    __shared__ __half Ks[AKT][QKP];
    __shared__ __half Vt[HD][VTP];

    int h = blockIdx.y;
    int q0 = blockIdx.x * AQT;
    int tid = threadIdx.x, lane = tid & 31, warp = tid >> 5;
    int fr = lane >> 2, fc = lane & 3;
    const float scale = 0.11785113019775793f;

    const __half* Q = QKV + h * HD;
    const __half* K = QKV + H + h * HD;
    const __half* V = QKV + 2 * H + h * HD;

    {
        uint4 z = make_uint4(0, 0, 0, 0);
        for (int i = tid; i < AQT * QKP / 8; i += 128) ((uint4*)&Qs[0][0])[i] = z;
        for (int i = tid; i < AKT * QKP / 8; i += 128) ((uint4*)&Ks[0][0])[i] = z;
        for (int i = tid; i < HD * VTP / 8; i += 128) ((uint4*)&Vt[0][0])[i] = z;
    }
    __syncthreads();

    for (int i = tid; i < AQT * 9; i += 128) {
        int r = i / 9, c = i - r * 9;
        *(uint4*)&Qs[r][c * 8] = *(const uint4*)&Q[(size_t)(q0 + r) * QKVN + c * 8];
    }

    int rs0[2], rs1[2];
    rs0[0] = segs[q0 + warp * 16 + fr];     rs1[0] = sege[q0 + warp * 16 + fr];
    rs0[1] = segs[q0 + warp * 16 + fr + 8]; rs1[1] = sege[q0 + warp * 16 + fr + 8];
    float m[2] = {-3.0e38f, -3.0e38f};
    float l[2] = {0.f, 0.f};
    float out[9][4];
#pragma unroll
    for (int nt = 0; nt < 9; ++nt)
#pragma unroll
        for (int i = 0; i < 4; ++i) out[nt][i] = 0.f;

    int kstart = segs[q0];
    int kend = sege[q0 + AQT - 1];

    for (int c0 = kstart; c0 < kend; c0 += AKT) {
        int len = min(AKT, kend - c0);
        __syncthreads();

        for (int i = tid; i < len * 9; i += 128) {
            int r = i / 9, c = i - r * 9;
            *(uint4*)&Ks[r][c * 8] = *(const uint4*)&K[(size_t)(c0 + r) * QKVN + c * 8];
        }
        for (int i = tid; i < len * HD; i += 128) {
            int r = i / HD, d = i - r * HD;
            Vt[d][r] = V[(size_t)(c0 + r) * QKVN + d];
        }
        __syncthreads();

        float sc[8][4];
#pragma unroll
        for (int nt = 0; nt < 8; ++nt)
#pragma unroll
            for (int i = 0; i < 4; ++i) sc[nt][i] = 0.f;

#pragma unroll
        for (int kk = 0; kk < 5; ++kk) {
            int kb = kk * 16;
            uint32_t a[4];
            a[0] = *(const uint32_t*)&Qs[warp * 16 + fr][kb + fc * 2];
            a[1] = *(const uint32_t*)&Qs[warp * 16 + fr + 8][kb + fc * 2];
            a[2] = *(const uint32_t*)&Qs[warp * 16 + fr][kb + fc * 2 + 8];
            a[3] = *(const uint32_t*)&Qs[warp * 16 + fr + 8][kb + fc * 2 + 8];
#pragma unroll
            for (int nt = 0; nt < 8; ++nt) {
                uint32_t b[2];
                b[0] = *(const uint32_t*)&Ks[nt * 8 + fr][kb + fc * 2];
                b[1] = *(const uint32_t*)&Ks[nt * 8 + fr][kb + fc * 2 + 8];
                mma_f16(sc[nt], a, b);
            }
        }

        float mx0 = -3.0e38f, mx1 = -3.0e38f;
#pragma unroll
        for (int nt = 0; nt < 8; ++nt) {
            int kg0 = c0 + nt * 8 + fc * 2;
            int kg1 = kg0 + 1;
            sc[nt][0] = (kg0 >= rs0[0] && kg0 < rs1[0]) ? sc[nt][0] * scale : -3.0e38f;
            sc[nt][1] = (kg1 >= rs0[0] && kg1 < rs1[0]) ? sc[nt][1] * scale : -3.0e38f;
            sc[nt][2] = (kg0 >= rs0[1] && kg0 < rs1[1]) ? sc[nt][2] * scale : -3.0e38f;
            sc[nt][3] = (kg1 >= rs0[1] && kg1 < rs1[1]) ? sc[nt][3] * scale : -3.0e38f;
            mx0 = fmaxf(mx0, fmaxf(sc[nt][0], sc[nt][1]));
            mx1 = fmaxf(mx1, fmaxf(sc[nt][2], sc[nt][3]));
        }
#pragma unroll
        for (int ofs = 1; ofs <= 2; ofs <<= 1) {
            mx0 = fmaxf(mx0, __shfl_xor_sync(0xffffffffu, mx0, ofs));
            mx1 = fmaxf(mx1, __shfl_xor_sync(0xffffffffu, mx1, ofs));
        }
        float mnew0 = fmaxf(m[0], mx0);
        float mnew1 = fmaxf(m[1], mx1);
        float corr0 = __expf(m[0] - mnew0);
        float corr1 = __expf(m[1] - mnew1);

        float ps0 = 0.f, ps1 = 0.f;
#pragma unroll
        for (int nt = 0; nt < 8; ++nt) {
            sc[nt][0] = (sc[nt][0] > -1.0e38f) ? __expf(sc[nt][0] - mnew0) : 0.f;
            sc[nt][1] = (sc[nt][1] > -1.0e38f) ? __expf(sc[nt][1] - mnew0) : 0.f;
            sc[nt][2] = (sc[nt][2] > -1.0e38f) ? __expf(sc[nt][2] - mnew1) : 0.f;
            sc[nt][3] = (sc[nt][3] > -1.0e38f) ? __expf(sc[nt][3] - mnew1) : 0.f;
            ps0 += sc[nt][0] + sc[nt][1];
            ps1 += sc[nt][2] + sc[nt][3];
        }
#pragma unroll
        for (int ofs = 1; ofs <= 2; ofs <<= 1) {
            ps0 += __shfl_xor_sync(0xffffffffu, ps0, ofs);
            ps1 += __shfl_xor_sync(0xffffffffu, ps1, ofs);
        }
        l[0] = l[0] * corr0 + ps0;
        l[1] = l[1] * corr1 + ps1;
        m[0] = mnew0;
        m[1] = mnew1;

#pragma unroll
        for (int nt = 0; nt < 9; ++nt) {
            out[nt][0] *= corr0; out[nt][1] *= corr0;
            out[nt][2] *= corr1; out[nt][3] *= corr1;
        }
        uint32_t pr0[8], pr1[8];
#pragma unroll
        for (int nt = 0; nt < 8; ++nt) {
            __half2 h0 = __floats2half2_rn(sc[nt][0], sc[nt][1]);
            __half2 h1 = __floats2half2_rn(sc[nt][2], sc[nt][3]);
            pr0[nt] = *(uint32_t*)&h0;
            pr1[nt] = *(uint32_t*)&h1;
        }
#pragma unroll
        for (int j = 0; j < 4; ++j) {
            uint32_t a[4] = {pr0[2 * j], pr1[2 * j], pr0[2 * j + 1], pr1[2 * j + 1]};
            int kb = j * 16;
#pragma unroll
            for (int nt = 0; nt < 9; ++nt) {
                uint32_t b[2];
                b[0] = *(const uint32_t*)&Vt[nt * 8 + fr][kb + fc * 2];
                b[1] = *(const uint32_t*)&Vt[nt * 8 + fr][kb + fc * 2 + 8];
                mma_f16(out[nt], a, b);
            }
        }
    }

    float inv0 = 1.f / l[0];
    float inv1 = 1.f / l[1];
    size_t base0 = (size_t)(q0 + warp * 16 + fr) * H + h * HD;
    size_t base1 = (size_t)(q0 + warp * 16 + fr + 8) * H + h * HD;
#pragma unroll
    for (int nt = 0; nt < 9; ++nt) {
        int col = nt * 8 + fc * 2;
        __half2 o0 = __floats2half2_rn(out[nt][0] * inv0, out[nt][1] * inv0);
        __half2 o1 = __floats2half2_rn(out[nt][2] * inv1, out[nt][3] * inv1);
        *(__half2*)&O[base0 + col] = o0;
        *(__half2*)&O[base1 + col] = o1;
    }
}

// ---------------- launch ----------------
extern "C" void kernel_launch(void* const* d_in, const int* in_sizes, int n_in,
                              void* d_out, int out_size) {
    const float* hs    = (const float*)d_in[0];
    const int*   doc   = (const int*)d_in[1];
    const float* q_w   = (const float*)d_in[2];
    const float* q_b   = (const float*)d_in[3];
    const float* k_w   = (const float*)d_in[4];
    const float* k_b   = (const float*)d_in[5];
    const float* v_w   = (const float*)d_in[6];
    const float* v_b   = (const float*)d_in[7];
    const float* o_w   = (const float*)d_in[8];
    const float* o_b   = (const float*)d_in[9];
    const float* ln1_g = (const float*)d_in[10];
    const float* ln1_b = (const float*)d_in[11];
    const float* ln2_g = (const float*)d_in[12];
    const float* ln2_b = (const float*)d_in[13];
    const float* fc1_w = (const float*)d_in[14];
    const float* fc1_b = (const float*)d_in[15];
    const float* fc2_w = (const float*)d_in[16];
    const float* fc2_b = (const float*)d_in[17];
    float* out = (float*)d_out;

    __half *xnh, *qkvh, *attnh, *yh, *ffh;
    __half *wqkvh, *owh, *fc1h, *fc2h;
    float *hid, *bqkv;
    int *segs, *sege;
    cudaGetSymbolAddress((void**)&xnh,   g_xnh);
    cudaGetSymbolAddress((void**)&qkvh,  g_qkvh);
    cudaGetSymbolAddress((void**)&attnh, g_attnh);
    cudaGetSymbolAddress((void**)&hid,   g_hid);
    cudaGetSymbolAddress((void**)&yh,    g_yh);
    cudaGetSymbolAddress((void**)&ffh,   g_ffh);
    cudaGetSymbolAddress((void**)&wqkvh, g_wqkvh);
    cudaGetSymbolAddress((void**)&owh,   g_owh);
    cudaGetSymbolAddress((void**)&fc1h,  g_fc1h);
    cudaGetSymbolAddress((void**)&fc2h,  g_fc2h);
    cudaGetSymbolAddress((void**)&bqkv,  g_bqkv);
    cudaGetSymbolAddress((void**)&segs,  g_segs);
    cudaGetSymbolAddress((void**)&sege,  g_sege);

    static bool attr_set = false;
    if (!attr_set) {
        cudaFuncSetAttribute(gemm_f16, cudaFuncAttributeMaxDynamicSharedMemorySize, GEMM_SMEM);
        attr_set = true;
    }

    int nHH4 = H * H / 4;
    int nHF4 = H * FF / 4;
    cvt_f2h4<<<dim3((nHH4 + 255) / 256, 4), 256>>>(
        (const float4*)q_w, (const float4*)k_w, (const float4*)v_w, (const float4*)o_w,
        (__half2*)wqkvh, (__half2*)(wqkvh + (size_t)H * H),
        (__half2*)(wqkvh + (size_t)2 * H * H), (__half2*)owh, nHH4);
    cvt_f2h<<<(nHF4 + 255) / 256, 256>>>((const float4*)fc1_w, (__half2*)fc1h, nHF4);
    cvt_f2h<<<(nHF4 + 255) / 256, 256>>>((const float4*)fc2_w, (__half2*)fc2h, nHF4);
    pack_bias<<<(H + 255) / 256, 256>>>(q_b, k_b, v_b, bqkv);

    dim3 gQKV(QKVN / BN, S / BM);            // (27, 32)
    dim3 gH(H / BN, S / BM);                 // (9, 32)
    dim3 gF((FF + BN - 1) / BN, S / BM);     // (34, 32)

    ln_kernel_h<<<S, 256>>>(hs, ln1_g, ln1_b, xnh);
    doc_ranges<<<(S + 255) / 256, 256>>>(doc, segs, sege);

    gemm_f16<<<gQKV, 256, GEMM_SMEM>>>(xnh, wqkvh, bqkv, nullptr, nullptr, qkvh, S, QKVN, H, 0);

    attn_mma<<<dim3(S / AQT, NH), 128>>>(qkvh, segs, sege, attnh);

    gemm_f16<<<gH, 256, GEMM_SMEM>>>(attnh, owh, o_b, hs, hid, nullptr, S, H, H, 2);

    ln_kernel_h<<<S, 256>>>(hid, ln2_g, ln2_b, yh);

    gemm_f16<<<gF, 256, GEMM_SMEM>>>(yh, fc1h, fc1_b, nullptr, nullptr, ffh, S, FF, H, 1);
    gemm_f16<<<gH, 256, GEMM_SMEM>>>(ffh, fc2h, fc2_b, hid, out, nullptr, S, H, FF, 2);
}